// round 13
// baseline (speedup 1.0000x reference)
#include <cuda_runtime.h>
#include <cuda_fp16.h>
#include <mma.h>
#include <stdint.h>

using namespace nvcuda;

#define Nn 100000
#define Ee 1600000
#define Gg 512
#define Hh 128
#define NB_SCAN ((Nn + 1023) / 1024)   /* 98 */
#define CDIV(a,b) (((a)+(b)-1)/(b))

// ---------------- scratch (static device globals; no runtime alloc) ----------------
__device__ __align__(16) __half g_f16X[(size_t)Nn * Hh];   // layer input (norm_out-scaled)
__device__ __align__(16) __half g_f16A[(size_t)Nn * Hh];
__device__ __align__(16) __half g_f16B[(size_t)Nn * Hh];
__device__ __align__(16) __half g_f16Agg[(size_t)Nn * Hh]; // aggregation output
__device__ __align__(16) __half g_whi[3 * 16384];          // W[k][n] dense fp16 hi
__device__ __align__(16) __half g_wlo[3 * 16384];          // (W - hi) * 1024 dense fp16
__device__ float g_norm_out[Nn];
__device__ float g_norm_in[Nn];
__device__ int   g_outdeg[Nn];
__device__ int   g_indeg[Nn];
__device__ int   g_cursor[Nn];
__device__ int   g_rowstart[Nn + 1];
__device__ int   g_esrc[Ee];
__device__ int   g_scan_flag[NB_SCAN];   // 0=none, 1=aggregate ready, 2=inclusive ready
__device__ int   g_scan_agg[NB_SCAN];
__device__ int   g_scan_inc[NB_SCAN];
__device__ __align__(16) float g_gsum[Gg * Hh];

// ---------------- init (zero counters/flags/gsum) + convert W -> split fp16 ----------
__global__ void initcw_kernel(const float* __restrict__ W0, const float* __restrict__ W1,
                              const float* __restrict__ W2) {
    int i = blockIdx.x * blockDim.x + threadIdx.x;
    if (i < Nn) { g_indeg[i] = 0; g_outdeg[i] = 0; g_cursor[i] = 0; }
    if (i < Gg * Hh) g_gsum[i] = 0.0f;
    if (i < NB_SCAN) g_scan_flag[i] = 0;
    if (i < 3 * 16384) {
        int l = i >> 14, idx = i & 16383;
        const float* W = (l == 0) ? W0 : ((l == 1) ? W1 : W2);
        float w = W[idx];
        __half hi = __float2half_rn(w);
        __half lo = __float2half_rn((w - __half2float(hi)) * 1024.0f);
        g_whi[i] = hi;
        g_wlo[i] = lo;
    }
}

// ---------------- degrees ----------------
__global__ void degree_kernel(const int* __restrict__ src, const int* __restrict__ dst) {
    int e = blockIdx.x * blockDim.x + threadIdx.x;
    if (e >= Ee) return;
    atomicAdd(&g_outdeg[src[e]], 1);
    atomicAdd(&g_indeg[dst[e]], 1);
}

__global__ void norm_kernel() {
    int i = blockIdx.x * blockDim.x + threadIdx.x;
    if (i >= Nn) return;
    g_norm_out[i] = rsqrtf(fmaxf((float)g_outdeg[i], 1.0f));
    g_norm_in[i]  = rsqrtf(fmaxf((float)g_indeg[i], 1.0f));
}

// ---------------- convert x -> fp16 pre-scaled by norm_out ----------------
__global__ void convert_x_kernel(const float* __restrict__ x) {
    int i = blockIdx.x * blockDim.x + threadIdx.x;   // one float4 per thread
    if (i >= Nn * 32) return;
    int n = i >> 5;
    float no = g_norm_out[n];
    float4 v = reinterpret_cast<const float4*>(x)[i];
    __half2 a = __floats2half2_rn(v.x * no, v.y * no);
    __half2 b = __floats2half2_rn(v.z * no, v.w * no);
    uint2 p;
    p.x = *reinterpret_cast<unsigned int*>(&a);
    p.y = *reinterpret_cast<unsigned int*>(&b);
    reinterpret_cast<uint2*>(g_f16X)[i] = p;
}

// ---------------- single-pass scan of indeg -> rowstart (decoupled lookback) -------
// 98 blocks x 1024 threads; all blocks resident simultaneously -> lookback safe.
__global__ void scan_lookback_kernel() {
    __shared__ int sh[1024];
    __shared__ int s_prev;
    int tid = threadIdx.x, b = blockIdx.x;
    int idx = b * 1024 + tid;
    int v = (idx < Nn) ? g_indeg[idx] : 0;
    sh[tid] = v;
    __syncthreads();
    #pragma unroll
    for (int off = 1; off < 1024; off <<= 1) {
        int t = 0;
        if (tid >= off) t = sh[tid - off];
        __syncthreads();
        if (tid >= off) sh[tid] += t;
        __syncthreads();
    }
    // publish aggregate (block 0 publishes inclusive immediately)
    if (tid == 1023) {
        if (b == 0) {
            g_scan_inc[0] = sh[1023];
            __threadfence();
            g_scan_flag[0] = 2;
        } else {
            g_scan_agg[b] = sh[1023];
            __threadfence();
            g_scan_flag[b] = 1;
        }
    }
    if (tid == 0) {
        int sum = 0;
        if (b > 0) {
            int j = b - 1;
            while (true) {
                int f;
                do { f = ((volatile int*)g_scan_flag)[j]; } while (f == 0);
                __threadfence();
                if (f == 2) { sum += ((volatile int*)g_scan_inc)[j]; break; }
                sum += ((volatile int*)g_scan_agg)[j];
                j--;
            }
        }
        s_prev = sum;
    }
    __syncthreads();
    int prev = s_prev;
    if (idx < Nn) g_rowstart[idx] = prev + sh[tid] - v;   // exclusive prefix
    if (tid == 1023 && b > 0) {
        g_scan_inc[b] = prev + sh[1023];
        __threadfence();
        g_scan_flag[b] = 2;
    }
    if (idx == 0) g_rowstart[Nn] = Ee;
}

// ---------------- bucket edges by dst ----------------
__global__ void bucket_kernel(const int* __restrict__ src, const int* __restrict__ dst) {
    int e = blockIdx.x * blockDim.x + threadIdx.x;
    if (e >= Ee) return;
    int d = dst[e];
    int pos = g_rowstart[d] + atomicAdd(&g_cursor[d], 1);
    g_esrc[pos] = src[e];
}

// ---------------- aggregation: warp per node, fp16 gather, x4 unrolled ----------------
__global__ void agg_kernel(const __half* __restrict__ hin, __half* __restrict__ hout) {
    int w = (blockIdx.x * blockDim.x + threadIdx.x) >> 5;
    int lane = threadIdx.x & 31;
    if (w >= Nn) return;
    int beg = g_rowstart[w], end = g_rowstart[w + 1];
    float4 acc = make_float4(0.f, 0.f, 0.f, 0.f);
    const uint2* base = reinterpret_cast<const uint2*>(hin);
    int e = beg;
    for (; e + 3 < end; e += 4) {
        int s0 = g_esrc[e + 0], s1 = g_esrc[e + 1];
        int s2 = g_esrc[e + 2], s3 = g_esrc[e + 3];
        uint2 p0 = base[(size_t)s0 * 32 + lane];
        uint2 p1 = base[(size_t)s1 * 32 + lane];
        uint2 p2 = base[(size_t)s2 * 32 + lane];
        uint2 p3 = base[(size_t)s3 * 32 + lane];
        float2 a0 = __half22float2(*reinterpret_cast<__half2*>(&p0.x));
        float2 b0 = __half22float2(*reinterpret_cast<__half2*>(&p0.y));
        float2 a1 = __half22float2(*reinterpret_cast<__half2*>(&p1.x));
        float2 b1 = __half22float2(*reinterpret_cast<__half2*>(&p1.y));
        float2 a2 = __half22float2(*reinterpret_cast<__half2*>(&p2.x));
        float2 b2 = __half22float2(*reinterpret_cast<__half2*>(&p2.y));
        float2 a3 = __half22float2(*reinterpret_cast<__half2*>(&p3.x));
        float2 b3 = __half22float2(*reinterpret_cast<__half2*>(&p3.y));
        acc.x += (a0.x + a1.x) + (a2.x + a3.x);
        acc.y += (a0.y + a1.y) + (a2.y + a3.y);
        acc.z += (b0.x + b1.x) + (b2.x + b3.x);
        acc.w += (b0.y + b1.y) + (b2.y + b3.y);
    }
    for (; e < end; e++) {
        int s = g_esrc[e];
        uint2 p = base[(size_t)s * 32 + lane];
        float2 a = __half22float2(*reinterpret_cast<__half2*>(&p.x));
        float2 b = __half22float2(*reinterpret_cast<__half2*>(&p.y));
        acc.x += a.x; acc.y += a.y; acc.z += b.x; acc.w += b.y;
    }
    __half2 h0 = __floats2half2_rn(acc.x, acc.y);
    __half2 h1 = __floats2half2_rn(acc.z, acc.w);
    uint2 pk;
    pk.x = *reinterpret_cast<unsigned int*>(&h0);
    pk.y = *reinterpret_cast<unsigned int*>(&h1);
    reinterpret_cast<uint2*>(hout)[(size_t)w * 32 + lane] = pk;
}

// ---------------- tensor-core GEMM + epilogue, split-fp16 W (256 thr, BMg=128) ------
// C[128,128] = relu((A @ (Whi + Wlo/1024)) * norm_in + b)
// READOUT=false: * norm_out, fp16 store (feeds next layer's agg).
// READOUT=true : atomicAdd fp32 rows into g_gsum[n2g[row]] (graph sum readout fused).
#define BMg 128
#define LDA 136   /* halves, 272B row: 16B-multiple */
#define LDC 132   /* floats */
#define GEMM_SMEM ((BMg + 128 + 128) * LDA * 2)   /* 104448 B; Csm reuse needs 67584 */
template <bool READOUT>
__global__ __launch_bounds__(256) void gemm_tc_kernel(const __half* __restrict__ Ain,
                                                      const __half* __restrict__ whi,
                                                      const __half* __restrict__ wlo,
                                                      const float* __restrict__ bias,
                                                      __half* __restrict__ hout,
                                                      const int* __restrict__ n2g) {
    extern __shared__ char smraw[];
    __half* Asm = reinterpret_cast<__half*>(smraw);
    __half* Whi = Asm + BMg * LDA;
    __half* Wlo = Whi + 128 * LDA;
    float*  Csm = reinterpret_cast<float*>(smraw);   // reused after mainloop

    int tid = threadIdx.x;
    int warp = tid >> 5;
    int row0 = blockIdx.x * BMg;

    // stage A tile: 128 rows x 16 uint4
    #pragma unroll
    for (int i = tid; i < 2048; i += 256) {
        int r = i >> 4, c = i & 15;
        int grow = row0 + r;
        uint4 v = make_uint4(0u, 0u, 0u, 0u);
        if (grow < Nn) v = reinterpret_cast<const uint4*>(Ain + (size_t)grow * Hh)[c];
        *reinterpret_cast<uint4*>(Asm + r * LDA + c * 8) = v;
    }
    // stage Whi/Wlo: straight uint4 copies from precomputed dense fp16 images
    const uint4* wh4 = reinterpret_cast<const uint4*>(whi);
    const uint4* wl4 = reinterpret_cast<const uint4*>(wlo);
    #pragma unroll
    for (int i = tid; i < 2048; i += 256) {
        int r = i >> 4, c = i & 15;
        *reinterpret_cast<uint4*>(Whi + r * LDA + c * 8) = wh4[i];
        *reinterpret_cast<uint4*>(Wlo + r * LDA + c * 8) = wl4[i];
    }
    __syncthreads();

    int wm = warp >> 1;      // 0..3 -> rows wm*32
    int wn = warp & 1;       // 0..1 -> cols wn*64
    wmma::fragment<wmma::accumulator, 16, 16, 16, float> cfrag[2][4];
    #pragma unroll
    for (int i = 0; i < 2; i++)
        #pragma unroll
        for (int j = 0; j < 4; j++) wmma::fill_fragment(cfrag[i][j], 0.0f);

    // pass 1: A @ Wlo
    #pragma unroll
    for (int k0 = 0; k0 < 128; k0 += 16) {
        wmma::fragment<wmma::matrix_a, 16, 16, 16, __half, wmma::row_major> afrag[2];
        wmma::fragment<wmma::matrix_b, 16, 16, 16, __half, wmma::row_major> bfrag[4];
        #pragma unroll
        for (int i = 0; i < 2; i++)
            wmma::load_matrix_sync(afrag[i], Asm + (wm * 32 + i * 16) * LDA + k0, LDA);
        #pragma unroll
        for (int j = 0; j < 4; j++)
            wmma::load_matrix_sync(bfrag[j], Wlo + k0 * LDA + wn * 64 + j * 16, LDA);
        #pragma unroll
        for (int i = 0; i < 2; i++)
            #pragma unroll
            for (int j = 0; j < 4; j++)
                wmma::mma_sync(cfrag[i][j], afrag[i], bfrag[j], cfrag[i][j]);
    }
    // scale lo contribution down
    #pragma unroll
    for (int i = 0; i < 2; i++)
        #pragma unroll
        for (int j = 0; j < 4; j++)
            #pragma unroll
            for (int t = 0; t < cfrag[i][j].num_elements; t++)
                cfrag[i][j].x[t] *= (1.0f / 1024.0f);
    // pass 2: += A @ Whi
    #pragma unroll
    for (int k0 = 0; k0 < 128; k0 += 16) {
        wmma::fragment<wmma::matrix_a, 16, 16, 16, __half, wmma::row_major> afrag[2];
        wmma::fragment<wmma::matrix_b, 16, 16, 16, __half, wmma::row_major> bfrag[4];
        #pragma unroll
        for (int i = 0; i < 2; i++)
            wmma::load_matrix_sync(afrag[i], Asm + (wm * 32 + i * 16) * LDA + k0, LDA);
        #pragma unroll
        for (int j = 0; j < 4; j++)
            wmma::load_matrix_sync(bfrag[j], Whi + k0 * LDA + wn * 64 + j * 16, LDA);
        #pragma unroll
        for (int i = 0; i < 2; i++)
            #pragma unroll
            for (int j = 0; j < 4; j++)
                wmma::mma_sync(cfrag[i][j], afrag[i], bfrag[j], cfrag[i][j]);
    }
    __syncthreads();   // done reading Asm/W tiles; Csm aliases them

    #pragma unroll
    for (int i = 0; i < 2; i++)
        #pragma unroll
        for (int j = 0; j < 4; j++)
            wmma::store_matrix_sync(Csm + (wm * 32 + i * 16) * LDC + wn * 64 + j * 16,
                                    cfrag[i][j], LDC, wmma::mem_row_major);
    __syncthreads();

    // epilogue: thread t -> row r = t>>1, col block (t&1)*64
    {
        int r = tid >> 1;
        int half = tid & 1;
        int grow = row0 + r;
        if (grow < Nn) {
            float ni = g_norm_in[grow];
            const float4* Crow = reinterpret_cast<const float4*>(Csm + r * LDC) + half * 16;
            const float4* bias4 = reinterpret_cast<const float4*>(bias) + half * 16;
            if (READOUT) {
                // fused graph-sum readout: fp32 atomics into g_gsum
                int gid = n2g[grow];
                float* gb = g_gsum + gid * Hh + half * 64;
                #pragma unroll
                for (int j = 0; j < 8; j++) {
                    float4 v0 = Crow[2 * j + 0];
                    float4 v1 = Crow[2 * j + 1];
                    float4 b0 = bias4[2 * j + 0];
                    float4 b1 = bias4[2 * j + 1];
                    atomicAdd(gb + 8 * j + 0, fmaxf(v0.x * ni + b0.x, 0.f));
                    atomicAdd(gb + 8 * j + 1, fmaxf(v0.y * ni + b0.y, 0.f));
                    atomicAdd(gb + 8 * j + 2, fmaxf(v0.z * ni + b0.z, 0.f));
                    atomicAdd(gb + 8 * j + 3, fmaxf(v0.w * ni + b0.w, 0.f));
                    atomicAdd(gb + 8 * j + 4, fmaxf(v1.x * ni + b1.x, 0.f));
                    atomicAdd(gb + 8 * j + 5, fmaxf(v1.y * ni + b1.y, 0.f));
                    atomicAdd(gb + 8 * j + 6, fmaxf(v1.z * ni + b1.z, 0.f));
                    atomicAdd(gb + 8 * j + 7, fmaxf(v1.w * ni + b1.w, 0.f));
                }
            } else {
                float sc = g_norm_out[grow];
                uint4* orow = reinterpret_cast<uint4*>(hout + (size_t)grow * Hh) + half * 8;
                #pragma unroll
                for (int j = 0; j < 8; j++) {
                    float4 v0 = Crow[2 * j + 0];
                    float4 v1 = Crow[2 * j + 1];
                    float4 b0 = bias4[2 * j + 0];
                    float4 b1 = bias4[2 * j + 1];
                    float o0 = fmaxf(v0.x * ni + b0.x, 0.f) * sc;
                    float o1 = fmaxf(v0.y * ni + b0.y, 0.f) * sc;
                    float o2 = fmaxf(v0.z * ni + b0.z, 0.f) * sc;
                    float o3 = fmaxf(v0.w * ni + b0.w, 0.f) * sc;
                    float o4 = fmaxf(v1.x * ni + b1.x, 0.f) * sc;
                    float o5 = fmaxf(v1.y * ni + b1.y, 0.f) * sc;
                    float o6 = fmaxf(v1.z * ni + b1.z, 0.f) * sc;
                    float o7 = fmaxf(v1.w * ni + b1.w, 0.f) * sc;
                    __half2 p0 = __floats2half2_rn(o0, o1);
                    __half2 p1 = __floats2half2_rn(o2, o3);
                    __half2 p2 = __floats2half2_rn(o4, o5);
                    __half2 p3 = __floats2half2_rn(o6, o7);
                    uint4 pk;
                    pk.x = *reinterpret_cast<unsigned int*>(&p0);
                    pk.y = *reinterpret_cast<unsigned int*>(&p1);
                    pk.z = *reinterpret_cast<unsigned int*>(&p2);
                    pk.w = *reinterpret_cast<unsigned int*>(&p3);
                    orow[j] = pk;
                }
            }
        }
    }
}

// ---------------- MLP head ----------------
__global__ void mlp_kernel(const float* __restrict__ Wm1, const float* __restrict__ bm1,
                           const float* __restrict__ Wm2, const float* __restrict__ bm2,
                           float* __restrict__ out) {
    __shared__ float grow[Hh];
    __shared__ float red[Hh];
    int b = blockIdx.x, t = threadIdx.x;
    grow[t] = g_gsum[b * Hh + t];
    __syncthreads();
    float acc = 0.f;
    #pragma unroll
    for (int k = 0; k < Hh; k++) acc += grow[k] * Wm1[k * Hh + t];
    acc = fmaxf(acc + bm1[t], 0.f);
    red[t] = acc * Wm2[t];
    __syncthreads();
    #pragma unroll
    for (int s = 64; s > 0; s >>= 1) {
        if (t < s) red[t] += red[t + s];
        __syncthreads();
    }
    if (t == 0) out[b] = red[0] + bm2[0];
}

// ---------------- launch ----------------
extern "C" void kernel_launch(void* const* d_in, const int* in_sizes, int n_in,
                              void* d_out, int out_size) {
    const float* x   = (const float*)d_in[0];
    const int*   src = (const int*)d_in[1];
    const int*   dst = (const int*)d_in[2];
    const int*   n2g = (const int*)d_in[3];
    const float* W0  = (const float*)d_in[4];
    const float* b0  = (const float*)d_in[5];
    const float* W1  = (const float*)d_in[6];
    const float* b1  = (const float*)d_in[7];
    const float* W2  = (const float*)d_in[8];
    const float* b2  = (const float*)d_in[9];
    const float* Wm1 = (const float*)d_in[10];
    const float* bm1 = (const float*)d_in[11];
    const float* Wm2 = (const float*)d_in[12];
    const float* bm2 = (const float*)d_in[13];
    float* out = (float*)d_out;

    static __half *f16X = nullptr, *f16A = nullptr, *f16B = nullptr, *f16Agg = nullptr;
    static __half *whi = nullptr, *wlo = nullptr;
    if (!f16X) {
        cudaGetSymbolAddress((void**)&f16X,   g_f16X);
        cudaGetSymbolAddress((void**)&f16A,   g_f16A);
        cudaGetSymbolAddress((void**)&f16B,   g_f16B);
        cudaGetSymbolAddress((void**)&f16Agg, g_f16Agg);
        cudaGetSymbolAddress((void**)&whi,    g_whi);
        cudaGetSymbolAddress((void**)&wlo,    g_wlo);
        cudaFuncSetAttribute(gemm_tc_kernel<false>,
                             cudaFuncAttributeMaxDynamicSharedMemorySize, GEMM_SMEM);
        cudaFuncSetAttribute(gemm_tc_kernel<true>,
                             cudaFuncAttributeMaxDynamicSharedMemorySize, GEMM_SMEM);
    }

    initcw_kernel<<<CDIV(Nn, 256), 256>>>(W0, W1, W2);
    degree_kernel<<<CDIV(Ee, 256), 256>>>(src, dst);
    norm_kernel<<<CDIV(Nn, 256), 256>>>();
    convert_x_kernel<<<CDIV(Nn * 32, 256), 256>>>(x);
    scan_lookback_kernel<<<NB_SCAN, 1024>>>();
    bucket_kernel<<<CDIV(Ee, 256), 256>>>(src, dst);

    int agg_blocks = CDIV(Nn * 32, 256);
    int gemm_blocks = CDIV(Nn, BMg);

    agg_kernel<<<agg_blocks, 256>>>(f16X, f16Agg);
    gemm_tc_kernel<false><<<gemm_blocks, 256, GEMM_SMEM>>>(f16Agg, whi + 0 * 16384, wlo + 0 * 16384, b0, f16A, n2g);
    agg_kernel<<<agg_blocks, 256>>>(f16A, f16Agg);
    gemm_tc_kernel<false><<<gemm_blocks, 256, GEMM_SMEM>>>(f16Agg, whi + 1 * 16384, wlo + 1 * 16384, b1, f16B, n2g);
    agg_kernel<<<agg_blocks, 256>>>(f16B, f16Agg);
    gemm_tc_kernel<true ><<<gemm_blocks, 256, GEMM_SMEM>>>(f16Agg, whi + 2 * 16384, wlo + 2 * 16384, b2, f16X, n2g);

    mlp_kernel<<<Gg, Hh>>>(Wm1, bm1, Wm2, bm2, out);
}

// round 15
// speedup vs baseline: 1.4873x; 1.4873x over previous
#include <cuda_runtime.h>
#include <cuda_fp16.h>
#include <mma.h>
#include <stdint.h>

using namespace nvcuda;

#define Nn 100000
#define Ee 1600000
#define Gg 512
#define Hh 128
#define NB_SCAN ((Nn + 1023) / 1024)   /* 98 */
#define CDIV(a,b) (((a)+(b)-1)/(b))

// ---------------- scratch (static device globals; no runtime alloc) ----------------
__device__ __align__(16) __half g_f16X[(size_t)Nn * Hh];   // layer input (norm_out-scaled)
__device__ __align__(16) __half g_f16A[(size_t)Nn * Hh];
__device__ __align__(16) __half g_f16B[(size_t)Nn * Hh];
__device__ __align__(16) __half g_f16Agg[(size_t)Nn * Hh]; // aggregation output
__device__ __align__(16) __half g_whi[3 * 16384];          // W[k][n] dense fp16 hi
__device__ __align__(16) __half g_wlo[3 * 16384];          // (W - hi) * 1024 dense fp16
__device__ float g_norm_out[Nn];
__device__ float g_norm_in[Nn];
__device__ int   g_outdeg[Nn];
__device__ int   g_indeg[Nn];
__device__ int   g_cursor[Nn];
__device__ int   g_rowstart[Nn + 1];
__device__ int   g_esrc[Ee];
__device__ int   g_partials[128];
__device__ int   g_partoff[128];
__device__ __align__(16) float g_gsum[Gg * Hh];

// ---------------- init (zero counters/gsum) + convert W -> split fp16 ----------------
__global__ void initcw_kernel(const float* __restrict__ W0, const float* __restrict__ W1,
                              const float* __restrict__ W2) {
    int i = blockIdx.x * blockDim.x + threadIdx.x;
    if (i < Nn) { g_indeg[i] = 0; g_outdeg[i] = 0; g_cursor[i] = 0; }
    if (i < Gg * Hh) g_gsum[i] = 0.0f;
    if (i < 3 * 16384) {
        int l = i >> 14, idx = i & 16383;
        const float* W = (l == 0) ? W0 : ((l == 1) ? W1 : W2);
        float w = W[idx];
        __half hi = __float2half_rn(w);
        __half lo = __float2half_rn((w - __half2float(hi)) * 1024.0f);
        g_whi[i] = hi;
        g_wlo[i] = lo;
    }
}

// ---------------- degrees ----------------
__global__ void degree_kernel(const int* __restrict__ src, const int* __restrict__ dst) {
    int e = blockIdx.x * blockDim.x + threadIdx.x;
    if (e >= Ee) return;
    atomicAdd(&g_outdeg[src[e]], 1);
    atomicAdd(&g_indeg[dst[e]], 1);
}

// ---------------- scan of indeg (block phase) + degree norms ----------------
__global__ void scan_block_kernel() {
    __shared__ int sh[1024];
    int tid = threadIdx.x;
    int idx = blockIdx.x * 1024 + tid;
    int v = (idx < Nn) ? g_indeg[idx] : 0;
    if (idx < Nn) {
        g_norm_in[idx]  = rsqrtf(fmaxf((float)v, 1.0f));
        g_norm_out[idx] = rsqrtf(fmaxf((float)g_outdeg[idx], 1.0f));
    }
    sh[tid] = v;
    __syncthreads();
    #pragma unroll
    for (int off = 1; off < 1024; off <<= 1) {
        int t = 0;
        if (tid >= off) t = sh[tid - off];
        __syncthreads();
        if (tid >= off) sh[tid] += t;
        __syncthreads();
    }
    if (idx < Nn) g_rowstart[idx] = sh[tid] - v;
    if (tid == 1023) g_partials[blockIdx.x] = sh[1023];
}

__global__ void scan_partials_kernel() {
    __shared__ int sh[128];
    int t = threadIdx.x;
    int v = (t < NB_SCAN) ? g_partials[t] : 0;
    sh[t] = v;
    __syncthreads();
    #pragma unroll
    for (int off = 1; off < 128; off <<= 1) {
        int x = 0;
        if (t >= off) x = sh[t - off];
        __syncthreads();
        if (t >= off) sh[t] += x;
        __syncthreads();
    }
    g_partoff[t] = sh[t] - v;
}

__global__ void add_off_kernel() {
    int i = blockIdx.x * blockDim.x + threadIdx.x;
    if (i < Nn) g_rowstart[i] += g_partoff[i >> 10];
    if (i == 0) g_rowstart[Nn] = Ee;
}

// ---------------- convert x -> fp16 pre-scaled by norm_out ----------------
__global__ void convert_x_kernel(const float* __restrict__ x) {
    int i = blockIdx.x * blockDim.x + threadIdx.x;   // one float4 per thread
    if (i >= Nn * 32) return;
    int n = i >> 5;
    float no = g_norm_out[n];
    float4 v = reinterpret_cast<const float4*>(x)[i];
    __half2 a = __floats2half2_rn(v.x * no, v.y * no);
    __half2 b = __floats2half2_rn(v.z * no, v.w * no);
    uint2 p;
    p.x = *reinterpret_cast<unsigned int*>(&a);
    p.y = *reinterpret_cast<unsigned int*>(&b);
    reinterpret_cast<uint2*>(g_f16X)[i] = p;
}

// ---------------- bucket edges by dst ----------------
__global__ void bucket_kernel(const int* __restrict__ src, const int* __restrict__ dst) {
    int e = blockIdx.x * blockDim.x + threadIdx.x;
    if (e >= Ee) return;
    int d = dst[e];
    int pos = g_rowstart[d] + atomicAdd(&g_cursor[d], 1);
    g_esrc[pos] = src[e];
}

// ---------------- aggregation: warp per node, fp16 gather, x4 unrolled ----------------
__global__ void agg_kernel(const __half* __restrict__ hin, __half* __restrict__ hout) {
    int w = (blockIdx.x * blockDim.x + threadIdx.x) >> 5;
    int lane = threadIdx.x & 31;
    if (w >= Nn) return;
    int beg = g_rowstart[w], end = g_rowstart[w + 1];
    float4 acc = make_float4(0.f, 0.f, 0.f, 0.f);
    const uint2* base = reinterpret_cast<const uint2*>(hin);
    int e = beg;
    for (; e + 3 < end; e += 4) {
        int s0 = g_esrc[e + 0], s1 = g_esrc[e + 1];
        int s2 = g_esrc[e + 2], s3 = g_esrc[e + 3];
        uint2 p0 = base[(size_t)s0 * 32 + lane];
        uint2 p1 = base[(size_t)s1 * 32 + lane];
        uint2 p2 = base[(size_t)s2 * 32 + lane];
        uint2 p3 = base[(size_t)s3 * 32 + lane];
        float2 a0 = __half22float2(*reinterpret_cast<__half2*>(&p0.x));
        float2 b0 = __half22float2(*reinterpret_cast<__half2*>(&p0.y));
        float2 a1 = __half22float2(*reinterpret_cast<__half2*>(&p1.x));
        float2 b1 = __half22float2(*reinterpret_cast<__half2*>(&p1.y));
        float2 a2 = __half22float2(*reinterpret_cast<__half2*>(&p2.x));
        float2 b2 = __half22float2(*reinterpret_cast<__half2*>(&p2.y));
        float2 a3 = __half22float2(*reinterpret_cast<__half2*>(&p3.x));
        float2 b3 = __half22float2(*reinterpret_cast<__half2*>(&p3.y));
        acc.x += (a0.x + a1.x) + (a2.x + a3.x);
        acc.y += (a0.y + a1.y) + (a2.y + a3.y);
        acc.z += (b0.x + b1.x) + (b2.x + b3.x);
        acc.w += (b0.y + b1.y) + (b2.y + b3.y);
    }
    for (; e < end; e++) {
        int s = g_esrc[e];
        uint2 p = base[(size_t)s * 32 + lane];
        float2 a = __half22float2(*reinterpret_cast<__half2*>(&p.x));
        float2 b = __half22float2(*reinterpret_cast<__half2*>(&p.y));
        acc.x += a.x; acc.y += a.y; acc.z += b.x; acc.w += b.y;
    }
    __half2 h0 = __floats2half2_rn(acc.x, acc.y);
    __half2 h1 = __floats2half2_rn(acc.z, acc.w);
    uint2 pk;
    pk.x = *reinterpret_cast<unsigned int*>(&h0);
    pk.y = *reinterpret_cast<unsigned int*>(&h1);
    reinterpret_cast<uint2*>(hout)[(size_t)w * 32 + lane] = pk;
}

// ---------------- tensor-core GEMM + epilogue, split-fp16 W (256 thr, BMg=128) ------
// C[128,128] = relu((A @ (Whi + Wlo/1024)) * norm_in + b) [* norm_out], fp16 out.
// 8 warps: warp (wm,wn) computes 32x64 via 2x4 wmma 16x16x16 frags.
#define BMg 128
#define LDA 136   /* halves, 272B row: 16B-multiple */
#define LDC 132   /* floats */
#define GEMM_SMEM ((BMg + 128 + 128) * LDA * 2)   /* 104448 B; Csm reuse needs 67584 */
template <bool SCALED_OUT>
__global__ __launch_bounds__(256) void gemm_tc_kernel(const __half* __restrict__ Ain,
                                                      const __half* __restrict__ whi,
                                                      const __half* __restrict__ wlo,
                                                      const float* __restrict__ bias,
                                                      __half* __restrict__ hout) {
    extern __shared__ char smraw[];
    __half* Asm = reinterpret_cast<__half*>(smraw);
    __half* Whi = Asm + BMg * LDA;
    __half* Wlo = Whi + 128 * LDA;
    float*  Csm = reinterpret_cast<float*>(smraw);   // reused after mainloop

    int tid = threadIdx.x;
    int warp = tid >> 5;
    int row0 = blockIdx.x * BMg;

    // stage A tile: 128 rows x 16 uint4
    #pragma unroll
    for (int i = tid; i < 2048; i += 256) {
        int r = i >> 4, c = i & 15;
        int grow = row0 + r;
        uint4 v = make_uint4(0u, 0u, 0u, 0u);
        if (grow < Nn) v = reinterpret_cast<const uint4*>(Ain + (size_t)grow * Hh)[c];
        *reinterpret_cast<uint4*>(Asm + r * LDA + c * 8) = v;
    }
    // stage Whi/Wlo: straight uint4 copies from precomputed dense fp16 images
    const uint4* wh4 = reinterpret_cast<const uint4*>(whi);
    const uint4* wl4 = reinterpret_cast<const uint4*>(wlo);
    #pragma unroll
    for (int i = tid; i < 2048; i += 256) {
        int r = i >> 4, c = i & 15;
        *reinterpret_cast<uint4*>(Whi + r * LDA + c * 8) = wh4[i];
        *reinterpret_cast<uint4*>(Wlo + r * LDA + c * 8) = wl4[i];
    }
    __syncthreads();

    int wm = warp >> 1;      // 0..3 -> rows wm*32
    int wn = warp & 1;       // 0..1 -> cols wn*64
    wmma::fragment<wmma::accumulator, 16, 16, 16, float> cfrag[2][4];
    #pragma unroll
    for (int i = 0; i < 2; i++)
        #pragma unroll
        for (int j = 0; j < 4; j++) wmma::fill_fragment(cfrag[i][j], 0.0f);

    // pass 1: A @ Wlo
    #pragma unroll
    for (int k0 = 0; k0 < 128; k0 += 16) {
        wmma::fragment<wmma::matrix_a, 16, 16, 16, __half, wmma::row_major> afrag[2];
        wmma::fragment<wmma::matrix_b, 16, 16, 16, __half, wmma::row_major> bfrag[4];
        #pragma unroll
        for (int i = 0; i < 2; i++)
            wmma::load_matrix_sync(afrag[i], Asm + (wm * 32 + i * 16) * LDA + k0, LDA);
        #pragma unroll
        for (int j = 0; j < 4; j++)
            wmma::load_matrix_sync(bfrag[j], Wlo + k0 * LDA + wn * 64 + j * 16, LDA);
        #pragma unroll
        for (int i = 0; i < 2; i++)
            #pragma unroll
            for (int j = 0; j < 4; j++)
                wmma::mma_sync(cfrag[i][j], afrag[i], bfrag[j], cfrag[i][j]);
    }
    // scale lo contribution down
    #pragma unroll
    for (int i = 0; i < 2; i++)
        #pragma unroll
        for (int j = 0; j < 4; j++)
            #pragma unroll
            for (int t = 0; t < cfrag[i][j].num_elements; t++)
                cfrag[i][j].x[t] *= (1.0f / 1024.0f);
    // pass 2: += A @ Whi
    #pragma unroll
    for (int k0 = 0; k0 < 128; k0 += 16) {
        wmma::fragment<wmma::matrix_a, 16, 16, 16, __half, wmma::row_major> afrag[2];
        wmma::fragment<wmma::matrix_b, 16, 16, 16, __half, wmma::row_major> bfrag[4];
        #pragma unroll
        for (int i = 0; i < 2; i++)
            wmma::load_matrix_sync(afrag[i], Asm + (wm * 32 + i * 16) * LDA + k0, LDA);
        #pragma unroll
        for (int j = 0; j < 4; j++)
            wmma::load_matrix_sync(bfrag[j], Whi + k0 * LDA + wn * 64 + j * 16, LDA);
        #pragma unroll
        for (int i = 0; i < 2; i++)
            #pragma unroll
            for (int j = 0; j < 4; j++)
                wmma::mma_sync(cfrag[i][j], afrag[i], bfrag[j], cfrag[i][j]);
    }
    __syncthreads();   // done reading Asm/W tiles; Csm aliases them

    #pragma unroll
    for (int i = 0; i < 2; i++)
        #pragma unroll
        for (int j = 0; j < 4; j++)
            wmma::store_matrix_sync(Csm + (wm * 32 + i * 16) * LDC + wn * 64 + j * 16,
                                    cfrag[i][j], LDC, wmma::mem_row_major);
    __syncthreads();

    // epilogue: thread t -> row r = t>>1, col block (t&1)*64
    {
        int r = tid >> 1;
        int half = tid & 1;
        int grow = row0 + r;
        if (grow < Nn) {
            float ni = g_norm_in[grow];
            float sc = SCALED_OUT ? g_norm_out[grow] : 1.0f;
            const float4* Crow = reinterpret_cast<const float4*>(Csm + r * LDC) + half * 16;
            const float4* bias4 = reinterpret_cast<const float4*>(bias) + half * 16;
            uint4* orow = reinterpret_cast<uint4*>(hout + (size_t)grow * Hh) + half * 8;
            #pragma unroll
            for (int j = 0; j < 8; j++) {
                float4 v0 = Crow[2 * j + 0];
                float4 v1 = Crow[2 * j + 1];
                float4 b0 = bias4[2 * j + 0];
                float4 b1 = bias4[2 * j + 1];
                float o0 = fmaxf(v0.x * ni + b0.x, 0.f) * sc;
                float o1 = fmaxf(v0.y * ni + b0.y, 0.f) * sc;
                float o2 = fmaxf(v0.z * ni + b0.z, 0.f) * sc;
                float o3 = fmaxf(v0.w * ni + b0.w, 0.f) * sc;
                float o4 = fmaxf(v1.x * ni + b1.x, 0.f) * sc;
                float o5 = fmaxf(v1.y * ni + b1.y, 0.f) * sc;
                float o6 = fmaxf(v1.z * ni + b1.z, 0.f) * sc;
                float o7 = fmaxf(v1.w * ni + b1.w, 0.f) * sc;
                __half2 p0 = __floats2half2_rn(o0, o1);
                __half2 p1 = __floats2half2_rn(o2, o3);
                __half2 p2 = __floats2half2_rn(o4, o5);
                __half2 p3 = __floats2half2_rn(o6, o7);
                uint4 pk;
                pk.x = *reinterpret_cast<unsigned int*>(&p0);
                pk.y = *reinterpret_cast<unsigned int*>(&p1);
                pk.z = *reinterpret_cast<unsigned int*>(&p2);
                pk.w = *reinterpret_cast<unsigned int*>(&p3);
                orow[j] = pk;
            }
        }
    }
}

// ---------------- readout: warp per 16 consecutive nodes, run-batched atomics ----------------
__global__ void readout_kernel(const __half* __restrict__ h, const int* __restrict__ n2g) {
    int w = (blockIdx.x * blockDim.x + threadIdx.x) >> 5;
    int lane = threadIdx.x & 31;
    int n0 = w * 16;
    if (n0 >= Nn) return;
    int n1 = min(n0 + 16, Nn);
    float4 acc = make_float4(0.f, 0.f, 0.f, 0.f);
    int curg = n2g[n0];
    const uint2* base = reinterpret_cast<const uint2*>(h);
    for (int v = n0; v < n1; v++) {
        int gid = n2g[v];
        if (gid != curg) {
            float* gb = &g_gsum[curg * Hh + lane * 4];
            atomicAdd(gb + 0, acc.x); atomicAdd(gb + 1, acc.y);
            atomicAdd(gb + 2, acc.z); atomicAdd(gb + 3, acc.w);
            acc = make_float4(0.f, 0.f, 0.f, 0.f);
            curg = gid;
        }
        uint2 p = base[(size_t)v * 32 + lane];
        float2 f0 = __half22float2(*reinterpret_cast<__half2*>(&p.x));
        float2 f1 = __half22float2(*reinterpret_cast<__half2*>(&p.y));
        acc.x += f0.x; acc.y += f0.y; acc.z += f1.x; acc.w += f1.y;
    }
    float* gb = &g_gsum[curg * Hh + lane * 4];
    atomicAdd(gb + 0, acc.x); atomicAdd(gb + 1, acc.y);
    atomicAdd(gb + 2, acc.z); atomicAdd(gb + 3, acc.w);
}

// ---------------- MLP head ----------------
__global__ void mlp_kernel(const float* __restrict__ Wm1, const float* __restrict__ bm1,
                           const float* __restrict__ Wm2, const float* __restrict__ bm2,
                           float* __restrict__ out) {
    __shared__ float grow[Hh];
    __shared__ float red[Hh];
    int b = blockIdx.x, t = threadIdx.x;
    grow[t] = g_gsum[b * Hh + t];
    __syncthreads();
    float acc = 0.f;
    #pragma unroll
    for (int k = 0; k < Hh; k++) acc += grow[k] * Wm1[k * Hh + t];
    acc = fmaxf(acc + bm1[t], 0.f);
    red[t] = acc * Wm2[t];
    __syncthreads();
    #pragma unroll
    for (int s = 64; s > 0; s >>= 1) {
        if (t < s) red[t] += red[t + s];
        __syncthreads();
    }
    if (t == 0) out[b] = red[0] + bm2[0];
}

// ---------------- launch ----------------
extern "C" void kernel_launch(void* const* d_in, const int* in_sizes, int n_in,
                              void* d_out, int out_size) {
    const float* x   = (const float*)d_in[0];
    const int*   src = (const int*)d_in[1];
    const int*   dst = (const int*)d_in[2];
    const int*   n2g = (const int*)d_in[3];
    const float* W0  = (const float*)d_in[4];
    const float* b0  = (const float*)d_in[5];
    const float* W1  = (const float*)d_in[6];
    const float* b1  = (const float*)d_in[7];
    const float* W2  = (const float*)d_in[8];
    const float* b2  = (const float*)d_in[9];
    const float* Wm1 = (const float*)d_in[10];
    const float* bm1 = (const float*)d_in[11];
    const float* Wm2 = (const float*)d_in[12];
    const float* bm2 = (const float*)d_in[13];
    float* out = (float*)d_out;

    static __half *f16X = nullptr, *f16A = nullptr, *f16B = nullptr, *f16Agg = nullptr;
    static __half *whi = nullptr, *wlo = nullptr;
    if (!f16X) {
        cudaGetSymbolAddress((void**)&f16X,   g_f16X);
        cudaGetSymbolAddress((void**)&f16A,   g_f16A);
        cudaGetSymbolAddress((void**)&f16B,   g_f16B);
        cudaGetSymbolAddress((void**)&f16Agg, g_f16Agg);
        cudaGetSymbolAddress((void**)&whi,    g_whi);
        cudaGetSymbolAddress((void**)&wlo,    g_wlo);
        cudaFuncSetAttribute(gemm_tc_kernel<true>,
                             cudaFuncAttributeMaxDynamicSharedMemorySize, GEMM_SMEM);
        cudaFuncSetAttribute(gemm_tc_kernel<false>,
                             cudaFuncAttributeMaxDynamicSharedMemorySize, GEMM_SMEM);
    }

    initcw_kernel<<<CDIV(Nn, 256), 256>>>(W0, W1, W2);
    degree_kernel<<<CDIV(Ee, 256), 256>>>(src, dst);
    scan_block_kernel<<<NB_SCAN, 1024>>>();
    scan_partials_kernel<<<1, 128>>>();
    add_off_kernel<<<CDIV(Nn + 1, 256), 256>>>();
    convert_x_kernel<<<CDIV(Nn * 32, 256), 256>>>(x);
    bucket_kernel<<<CDIV(Ee, 256), 256>>>(src, dst);

    int agg_blocks = CDIV(Nn * 32, 256);
    int gemm_blocks = CDIV(Nn, BMg);

    agg_kernel<<<agg_blocks, 256>>>(f16X, f16Agg);
    gemm_tc_kernel<true ><<<gemm_blocks, 256, GEMM_SMEM>>>(f16Agg, whi + 0 * 16384, wlo + 0 * 16384, b0, f16A);
    agg_kernel<<<agg_blocks, 256>>>(f16A, f16Agg);
    gemm_tc_kernel<true ><<<gemm_blocks, 256, GEMM_SMEM>>>(f16Agg, whi + 1 * 16384, wlo + 1 * 16384, b1, f16B);
    agg_kernel<<<agg_blocks, 256>>>(f16B, f16Agg);
    gemm_tc_kernel<false><<<gemm_blocks, 256, GEMM_SMEM>>>(f16Agg, whi + 2 * 16384, wlo + 2 * 16384, b2, f16X);

    readout_kernel<<<CDIV(CDIV(Nn, 16) * 32, 256), 256>>>(f16X, n2g);
    mlp_kernel<<<Gg, Hh>>>(Wm1, bm1, Wm2, bm2, out);
}

// round 16
// speedup vs baseline: 1.5244x; 1.0250x over previous
#include <cuda_runtime.h>
#include <cuda_fp16.h>
#include <mma.h>
#include <stdint.h>

using namespace nvcuda;

#define Nn 100000
#define Ee 1600000
#define Gg 512
#define Hh 128
#define NB_SCAN ((Nn + 1023) / 1024)   /* 98 */
#define CDIV(a,b) (((a)+(b)-1)/(b))

// ---------------- scratch (static device globals; no runtime alloc) ----------------
__device__ __align__(16) __half g_f16X[(size_t)Nn * Hh];   // layer input (norm_out-scaled)
__device__ __align__(16) __half g_f16A[(size_t)Nn * Hh];
__device__ __align__(16) __half g_f16B[(size_t)Nn * Hh];
__device__ __align__(16) __half g_f16Agg[(size_t)Nn * Hh]; // aggregation output
__device__ __align__(16) __half g_whi[3 * 16384];          // W[k][n] dense fp16 hi
__device__ __align__(16) __half g_wlo[3 * 16384];          // (W - hi) * 1024 dense fp16
__device__ float g_norm_out[Nn];
__device__ float g_norm_in[Nn];
__device__ int   g_outdeg[Nn];
__device__ int   g_indeg[Nn];
__device__ int   g_cursor[Nn];
__device__ int   g_rowstart[Nn + 1];   // block-local exclusive prefix (+ sentinel at Nn)
__device__ int   g_esrc[Ee];
__device__ int   g_partials[128];
__device__ int   g_partoff[128];       // exclusive block offsets
__device__ __align__(16) float g_gsum[Gg * Hh];

// ---------------- init (zero counters/gsum) + convert W -> split fp16 ----------------
__global__ void initcw_kernel(const float* __restrict__ W0, const float* __restrict__ W1,
                              const float* __restrict__ W2) {
    int i = blockIdx.x * blockDim.x + threadIdx.x;
    if (i < Nn) { g_indeg[i] = 0; g_outdeg[i] = 0; g_cursor[i] = 0; }
    if (i < Gg * Hh) g_gsum[i] = 0.0f;
    if (i < 3 * 16384) {
        int l = i >> 14, idx = i & 16383;
        const float* W = (l == 0) ? W0 : ((l == 1) ? W1 : W2);
        float w = W[idx];
        __half hi = __float2half_rn(w);
        __half lo = __float2half_rn((w - __half2float(hi)) * 1024.0f);
        g_whi[i] = hi;
        g_wlo[i] = lo;
    }
}

// ---------------- degrees ----------------
__global__ void degree_kernel(const int* __restrict__ src, const int* __restrict__ dst) {
    int e = blockIdx.x * blockDim.x + threadIdx.x;
    if (e >= Ee) return;
    atomicAdd(&g_outdeg[src[e]], 1);
    atomicAdd(&g_indeg[dst[e]], 1);
}

// ---------------- scan of indeg (block-local phase) + degree norms ----------------
__global__ void scan_block_kernel() {
    __shared__ int sh[1024];
    int tid = threadIdx.x;
    int idx = blockIdx.x * 1024 + tid;
    int v = (idx < Nn) ? g_indeg[idx] : 0;
    if (idx < Nn) {
        g_norm_in[idx]  = rsqrtf(fmaxf((float)v, 1.0f));
        g_norm_out[idx] = rsqrtf(fmaxf((float)g_outdeg[idx], 1.0f));
    }
    sh[tid] = v;
    __syncthreads();
    #pragma unroll
    for (int off = 1; off < 1024; off <<= 1) {
        int t = 0;
        if (tid >= off) t = sh[tid - off];
        __syncthreads();
        if (tid >= off) sh[tid] += t;
        __syncthreads();
    }
    if (idx < Nn) g_rowstart[idx] = sh[tid] - v;   // block-local exclusive
    if (tid == 1023) g_partials[blockIdx.x] = sh[1023];
}

// partoff[t] = exclusive prefix of block sums; thread NB_SCAN-1 writes the sentinel:
// rowstart[Nn] + partoff[(Nn)>>10] must equal Ee.
__global__ void scan_partials_kernel() {
    __shared__ int sh[128];
    int t = threadIdx.x;
    int v = (t < NB_SCAN) ? g_partials[t] : 0;
    sh[t] = v;
    __syncthreads();
    #pragma unroll
    for (int off = 1; off < 128; off <<= 1) {
        int x = 0;
        if (t >= off) x = sh[t - off];
        __syncthreads();
        if (t >= off) sh[t] += x;
        __syncthreads();
    }
    int excl = sh[t] - v;
    g_partoff[t] = excl;
    if (t == (Nn >> 10)) g_rowstart[Nn] = Ee - excl;   // sentinel for agg's last node
}

// ---------------- fused: bucket edges by dst + convert x -> fp16*norm_out ----------
__global__ void bucketcx_kernel(const int* __restrict__ src, const int* __restrict__ dst,
                                const float* __restrict__ x) {
    int i = blockIdx.x * blockDim.x + threadIdx.x;
    if (i < Ee) {
        int d = dst[i];
        int pos = g_rowstart[d] + g_partoff[d >> 10] + atomicAdd(&g_cursor[d], 1);
        g_esrc[pos] = src[i];
    }
    if (i < Nn * 32) {
        int n = i >> 5;
        float no = g_norm_out[n];
        float4 v = reinterpret_cast<const float4*>(x)[i];
        __half2 a = __floats2half2_rn(v.x * no, v.y * no);
        __half2 b = __floats2half2_rn(v.z * no, v.w * no);
        uint2 p;
        p.x = *reinterpret_cast<unsigned int*>(&a);
        p.y = *reinterpret_cast<unsigned int*>(&b);
        reinterpret_cast<uint2*>(g_f16X)[i] = p;
    }
}

// ---------------- aggregation: warp per node, fp16 gather, x4 unrolled ----------------
__global__ void agg_kernel(const __half* __restrict__ hin, __half* __restrict__ hout) {
    int w = (blockIdx.x * blockDim.x + threadIdx.x) >> 5;
    int lane = threadIdx.x & 31;
    if (w >= Nn) return;
    int beg = g_rowstart[w] + g_partoff[w >> 10];
    int end = g_rowstart[w + 1] + g_partoff[(w + 1) >> 10];
    float4 acc = make_float4(0.f, 0.f, 0.f, 0.f);
    const uint2* base = reinterpret_cast<const uint2*>(hin);
    int e = beg;
    for (; e + 3 < end; e += 4) {
        int s0 = g_esrc[e + 0], s1 = g_esrc[e + 1];
        int s2 = g_esrc[e + 2], s3 = g_esrc[e + 3];
        uint2 p0 = base[(size_t)s0 * 32 + lane];
        uint2 p1 = base[(size_t)s1 * 32 + lane];
        uint2 p2 = base[(size_t)s2 * 32 + lane];
        uint2 p3 = base[(size_t)s3 * 32 + lane];
        float2 a0 = __half22float2(*reinterpret_cast<__half2*>(&p0.x));
        float2 b0 = __half22float2(*reinterpret_cast<__half2*>(&p0.y));
        float2 a1 = __half22float2(*reinterpret_cast<__half2*>(&p1.x));
        float2 b1 = __half22float2(*reinterpret_cast<__half2*>(&p1.y));
        float2 a2 = __half22float2(*reinterpret_cast<__half2*>(&p2.x));
        float2 b2 = __half22float2(*reinterpret_cast<__half2*>(&p2.y));
        float2 a3 = __half22float2(*reinterpret_cast<__half2*>(&p3.x));
        float2 b3 = __half22float2(*reinterpret_cast<__half2*>(&p3.y));
        acc.x += (a0.x + a1.x) + (a2.x + a3.x);
        acc.y += (a0.y + a1.y) + (a2.y + a3.y);
        acc.z += (b0.x + b1.x) + (b2.x + b3.x);
        acc.w += (b0.y + b1.y) + (b2.y + b3.y);
    }
    for (; e < end; e++) {
        int s = g_esrc[e];
        uint2 p = base[(size_t)s * 32 + lane];
        float2 a = __half22float2(*reinterpret_cast<__half2*>(&p.x));
        float2 b = __half22float2(*reinterpret_cast<__half2*>(&p.y));
        acc.x += a.x; acc.y += a.y; acc.z += b.x; acc.w += b.y;
    }
    __half2 h0 = __floats2half2_rn(acc.x, acc.y);
    __half2 h1 = __floats2half2_rn(acc.z, acc.w);
    uint2 pk;
    pk.x = *reinterpret_cast<unsigned int*>(&h0);
    pk.y = *reinterpret_cast<unsigned int*>(&h1);
    reinterpret_cast<uint2*>(hout)[(size_t)w * 32 + lane] = pk;
}

// ---------------- tensor-core GEMM + epilogue, split-fp16 W (256 thr, BMg=128) ------
// C[128,128] = relu((A @ (Whi + Wlo/1024)) * norm_in + b) [* norm_out], fp16 out.
// 8 warps: warp (wm,wn) computes 32x64 via 2x4 wmma 16x16x16 frags.
#define BMg 128
#define LDA 136   /* halves, 272B row: 16B-multiple */
#define LDC 132   /* floats */
#define GEMM_SMEM ((BMg + 128 + 128) * LDA * 2)   /* 104448 B; Csm reuse needs 67584 */
template <bool SCALED_OUT>
__global__ __launch_bounds__(256) void gemm_tc_kernel(const __half* __restrict__ Ain,
                                                      const __half* __restrict__ whi,
                                                      const __half* __restrict__ wlo,
                                                      const float* __restrict__ bias,
                                                      __half* __restrict__ hout) {
    extern __shared__ char smraw[];
    __half* Asm = reinterpret_cast<__half*>(smraw);
    __half* Whi = Asm + BMg * LDA;
    __half* Wlo = Whi + 128 * LDA;
    float*  Csm = reinterpret_cast<float*>(smraw);   // reused after mainloop

    int tid = threadIdx.x;
    int warp = tid >> 5;
    int row0 = blockIdx.x * BMg;

    // stage A tile: 128 rows x 16 uint4
    #pragma unroll
    for (int i = tid; i < 2048; i += 256) {
        int r = i >> 4, c = i & 15;
        int grow = row0 + r;
        uint4 v = make_uint4(0u, 0u, 0u, 0u);
        if (grow < Nn) v = reinterpret_cast<const uint4*>(Ain + (size_t)grow * Hh)[c];
        *reinterpret_cast<uint4*>(Asm + r * LDA + c * 8) = v;
    }
    // stage Whi/Wlo: straight uint4 copies from precomputed dense fp16 images
    const uint4* wh4 = reinterpret_cast<const uint4*>(whi);
    const uint4* wl4 = reinterpret_cast<const uint4*>(wlo);
    #pragma unroll
    for (int i = tid; i < 2048; i += 256) {
        int r = i >> 4, c = i & 15;
        *reinterpret_cast<uint4*>(Whi + r * LDA + c * 8) = wh4[i];
        *reinterpret_cast<uint4*>(Wlo + r * LDA + c * 8) = wl4[i];
    }
    __syncthreads();

    int wm = warp >> 1;      // 0..3 -> rows wm*32
    int wn = warp & 1;       // 0..1 -> cols wn*64
    wmma::fragment<wmma::accumulator, 16, 16, 16, float> cfrag[2][4];
    #pragma unroll
    for (int i = 0; i < 2; i++)
        #pragma unroll
        for (int j = 0; j < 4; j++) wmma::fill_fragment(cfrag[i][j], 0.0f);

    // pass 1: A @ Wlo
    #pragma unroll
    for (int k0 = 0; k0 < 128; k0 += 16) {
        wmma::fragment<wmma::matrix_a, 16, 16, 16, __half, wmma::row_major> afrag[2];
        wmma::fragment<wmma::matrix_b, 16, 16, 16, __half, wmma::row_major> bfrag[4];
        #pragma unroll
        for (int i = 0; i < 2; i++)
            wmma::load_matrix_sync(afrag[i], Asm + (wm * 32 + i * 16) * LDA + k0, LDA);
        #pragma unroll
        for (int j = 0; j < 4; j++)
            wmma::load_matrix_sync(bfrag[j], Wlo + k0 * LDA + wn * 64 + j * 16, LDA);
        #pragma unroll
        for (int i = 0; i < 2; i++)
            #pragma unroll
            for (int j = 0; j < 4; j++)
                wmma::mma_sync(cfrag[i][j], afrag[i], bfrag[j], cfrag[i][j]);
    }
    // scale lo contribution down
    #pragma unroll
    for (int i = 0; i < 2; i++)
        #pragma unroll
        for (int j = 0; j < 4; j++)
            #pragma unroll
            for (int t = 0; t < cfrag[i][j].num_elements; t++)
                cfrag[i][j].x[t] *= (1.0f / 1024.0f);
    // pass 2: += A @ Whi
    #pragma unroll
    for (int k0 = 0; k0 < 128; k0 += 16) {
        wmma::fragment<wmma::matrix_a, 16, 16, 16, __half, wmma::row_major> afrag[2];
        wmma::fragment<wmma::matrix_b, 16, 16, 16, __half, wmma::row_major> bfrag[4];
        #pragma unroll
        for (int i = 0; i < 2; i++)
            wmma::load_matrix_sync(afrag[i], Asm + (wm * 32 + i * 16) * LDA + k0, LDA);
        #pragma unroll
        for (int j = 0; j < 4; j++)
            wmma::load_matrix_sync(bfrag[j], Whi + k0 * LDA + wn * 64 + j * 16, LDA);
        #pragma unroll
        for (int i = 0; i < 2; i++)
            #pragma unroll
            for (int j = 0; j < 4; j++)
                wmma::mma_sync(cfrag[i][j], afrag[i], bfrag[j], cfrag[i][j]);
    }
    __syncthreads();   // done reading Asm/W tiles; Csm aliases them

    #pragma unroll
    for (int i = 0; i < 2; i++)
        #pragma unroll
        for (int j = 0; j < 4; j++)
            wmma::store_matrix_sync(Csm + (wm * 32 + i * 16) * LDC + wn * 64 + j * 16,
                                    cfrag[i][j], LDC, wmma::mem_row_major);
    __syncthreads();

    // epilogue: thread t -> row r = t>>1, col block (t&1)*64
    {
        int r = tid >> 1;
        int half = tid & 1;
        int grow = row0 + r;
        if (grow < Nn) {
            float ni = g_norm_in[grow];
            float sc = SCALED_OUT ? g_norm_out[grow] : 1.0f;
            const float4* Crow = reinterpret_cast<const float4*>(Csm + r * LDC) + half * 16;
            const float4* bias4 = reinterpret_cast<const float4*>(bias) + half * 16;
            uint4* orow = reinterpret_cast<uint4*>(hout + (size_t)grow * Hh) + half * 8;
            #pragma unroll
            for (int j = 0; j < 8; j++) {
                float4 v0 = Crow[2 * j + 0];
                float4 v1 = Crow[2 * j + 1];
                float4 b0 = bias4[2 * j + 0];
                float4 b1 = bias4[2 * j + 1];
                float o0 = fmaxf(v0.x * ni + b0.x, 0.f) * sc;
                float o1 = fmaxf(v0.y * ni + b0.y, 0.f) * sc;
                float o2 = fmaxf(v0.z * ni + b0.z, 0.f) * sc;
                float o3 = fmaxf(v0.w * ni + b0.w, 0.f) * sc;
                float o4 = fmaxf(v1.x * ni + b1.x, 0.f) * sc;
                float o5 = fmaxf(v1.y * ni + b1.y, 0.f) * sc;
                float o6 = fmaxf(v1.z * ni + b1.z, 0.f) * sc;
                float o7 = fmaxf(v1.w * ni + b1.w, 0.f) * sc;
                __half2 p0 = __floats2half2_rn(o0, o1);
                __half2 p1 = __floats2half2_rn(o2, o3);
                __half2 p2 = __floats2half2_rn(o4, o5);
                __half2 p3 = __floats2half2_rn(o6, o7);
                uint4 pk;
                pk.x = *reinterpret_cast<unsigned int*>(&p0);
                pk.y = *reinterpret_cast<unsigned int*>(&p1);
                pk.z = *reinterpret_cast<unsigned int*>(&p2);
                pk.w = *reinterpret_cast<unsigned int*>(&p3);
                orow[j] = pk;
            }
        }
    }
}

// ---------------- readout: warp per 16 consecutive nodes, run-batched atomics ----------------
__global__ void readout_kernel(const __half* __restrict__ h, const int* __restrict__ n2g) {
    int w = (blockIdx.x * blockDim.x + threadIdx.x) >> 5;
    int lane = threadIdx.x & 31;
    int n0 = w * 16;
    if (n0 >= Nn) return;
    int n1 = min(n0 + 16, Nn);
    float4 acc = make_float4(0.f, 0.f, 0.f, 0.f);
    int curg = n2g[n0];
    const uint2* base = reinterpret_cast<const uint2*>(h);
    for (int v = n0; v < n1; v++) {
        int gid = n2g[v];
        if (gid != curg) {
            float* gb = &g_gsum[curg * Hh + lane * 4];
            atomicAdd(gb + 0, acc.x); atomicAdd(gb + 1, acc.y);
            atomicAdd(gb + 2, acc.z); atomicAdd(gb + 3, acc.w);
            acc = make_float4(0.f, 0.f, 0.f, 0.f);
            curg = gid;
        }
        uint2 p = base[(size_t)v * 32 + lane];
        float2 f0 = __half22float2(*reinterpret_cast<__half2*>(&p.x));
        float2 f1 = __half22float2(*reinterpret_cast<__half2*>(&p.y));
        acc.x += f0.x; acc.y += f0.y; acc.z += f1.x; acc.w += f1.y;
    }
    float* gb = &g_gsum[curg * Hh + lane * 4];
    atomicAdd(gb + 0, acc.x); atomicAdd(gb + 1, acc.y);
    atomicAdd(gb + 2, acc.z); atomicAdd(gb + 3, acc.w);
}

// ---------------- MLP head ----------------
__global__ void mlp_kernel(const float* __restrict__ Wm1, const float* __restrict__ bm1,
                           const float* __restrict__ Wm2, const float* __restrict__ bm2,
                           float* __restrict__ out) {
    __shared__ float grow[Hh];
    __shared__ float red[Hh];
    int b = blockIdx.x, t = threadIdx.x;
    grow[t] = g_gsum[b * Hh + t];
    __syncthreads();
    float acc = 0.f;
    #pragma unroll
    for (int k = 0; k < Hh; k++) acc += grow[k] * Wm1[k * Hh + t];
    acc = fmaxf(acc + bm1[t], 0.f);
    red[t] = acc * Wm2[t];
    __syncthreads();
    #pragma unroll
    for (int s = 64; s > 0; s >>= 1) {
        if (t < s) red[t] += red[t + s];
        __syncthreads();
    }
    if (t == 0) out[b] = red[0] + bm2[0];
}

// ---------------- launch ----------------
extern "C" void kernel_launch(void* const* d_in, const int* in_sizes, int n_in,
                              void* d_out, int out_size) {
    const float* x   = (const float*)d_in[0];
    const int*   src = (const int*)d_in[1];
    const int*   dst = (const int*)d_in[2];
    const int*   n2g = (const int*)d_in[3];
    const float* W0  = (const float*)d_in[4];
    const float* b0  = (const float*)d_in[5];
    const float* W1  = (const float*)d_in[6];
    const float* b1  = (const float*)d_in[7];
    const float* W2  = (const float*)d_in[8];
    const float* b2  = (const float*)d_in[9];
    const float* Wm1 = (const float*)d_in[10];
    const float* bm1 = (const float*)d_in[11];
    const float* Wm2 = (const float*)d_in[12];
    const float* bm2 = (const float*)d_in[13];
    float* out = (float*)d_out;

    static __half *f16X = nullptr, *f16A = nullptr, *f16B = nullptr, *f16Agg = nullptr;
    static __half *whi = nullptr, *wlo = nullptr;
    if (!f16X) {
        cudaGetSymbolAddress((void**)&f16X,   g_f16X);
        cudaGetSymbolAddress((void**)&f16A,   g_f16A);
        cudaGetSymbolAddress((void**)&f16B,   g_f16B);
        cudaGetSymbolAddress((void**)&f16Agg, g_f16Agg);
        cudaGetSymbolAddress((void**)&whi,    g_whi);
        cudaGetSymbolAddress((void**)&wlo,    g_wlo);
        cudaFuncSetAttribute(gemm_tc_kernel<true>,
                             cudaFuncAttributeMaxDynamicSharedMemorySize, GEMM_SMEM);
        cudaFuncSetAttribute(gemm_tc_kernel<false>,
                             cudaFuncAttributeMaxDynamicSharedMemorySize, GEMM_SMEM);
    }

    initcw_kernel<<<CDIV(Nn, 256), 256>>>(W0, W1, W2);         // 1
    degree_kernel<<<CDIV(Ee, 256), 256>>>(src, dst);           // 2
    scan_block_kernel<<<NB_SCAN, 1024>>>();                    // 3
    scan_partials_kernel<<<1, 128>>>();                        // 4
    bucketcx_kernel<<<CDIV(Nn * 32, 256), 256>>>(src, dst, x); // 5 (Nn*32 > Ee)

    int agg_blocks = CDIV(Nn * 32, 256);
    int gemm_blocks = CDIV(Nn, BMg);

    agg_kernel<<<agg_blocks, 256>>>(f16X, f16Agg);             // 6 <- ncu -s 5 -c 1 lands here
    gemm_tc_kernel<true ><<<gemm_blocks, 256, GEMM_SMEM>>>(f16Agg, whi + 0 * 16384, wlo + 0 * 16384, b0, f16A);
    agg_kernel<<<agg_blocks, 256>>>(f16A, f16Agg);
    gemm_tc_kernel<true ><<<gemm_blocks, 256, GEMM_SMEM>>>(f16Agg, whi + 1 * 16384, wlo + 1 * 16384, b1, f16B);
    agg_kernel<<<agg_blocks, 256>>>(f16B, f16Agg);
    gemm_tc_kernel<false><<<gemm_blocks, 256, GEMM_SMEM>>>(f16Agg, whi + 2 * 16384, wlo + 2 * 16384, b2, f16X);

    readout_kernel<<<CDIV(CDIV(Nn, 16) * 32, 256), 256>>>(f16X, n2g);
    mlp_kernel<<<Gg, Hh>>>(Wm1, bm1, Wm2, bm2, out);
}